// round 1
// baseline (speedup 1.0000x reference)
#include <cuda_runtime.h>
#include <math.h>
#include <stdint.h>

// Problem constants
#define Bc 4
#define Sc 2048
#define Dc 1024
#define Hc 4096
#define Ec 8
#define Tc (Bc*Sc)          // 8192 tokens
#define NSLOT (2*Tc)        // 16384 (token, k) slots

// ---------------- device scratch (static, no allocs) ----------------
__device__ float  g_M[Dc*Ec];          // ctx_W @ r_W
__device__ float  g_v[Ec];             // q_W @ r_W
__device__ float  g_Kc[Ec];            // (ctx_b+q_b)@r_W + r_b
__device__ int    g_cnt[Ec];           // tokens-slots per expert
__device__ int    g_slots[Ec*Tc];      // slot ids per expert (slot = 2*t + k)
__device__ float  g_gate[NSLOT];       // gate per slot
__device__ double g_aux[Ec + 2];       // sum_p[8], sum_lse2, sum_ent
__device__ float  g_Hbuf[(size_t)NSLOT * Hc]; // 256 MiB intermediate
__device__ float  g_Ybuf[(size_t)NSLOT * Dc]; // 64 MiB per-slot outputs

// ---------------- init ----------------
__global__ void k_init() {
    int i = threadIdx.x;
    if (i < Ec) g_cnt[i] = 0;
    if (i < Ec + 2) g_aux[i] = 0.0;
}

// ---------------- router precompute: M, v, Kc ----------------
__global__ void k_prep(const float* __restrict__ ctxW,
                       const float* __restrict__ rW,
                       const float* __restrict__ qW,
                       const float* __restrict__ ctx_b,
                       const float* __restrict__ q_b,
                       const float* __restrict__ r_b) {
    int bid = blockIdx.x, tid = threadIdx.x;
    int wid = tid >> 5, lane = tid & 31;
    float p[Ec];
#pragma unroll
    for (int e = 0; e < Ec; e++) p[e] = 0.f;

    if (bid < Dc) {
        const float* row = ctxW + (size_t)bid * Dc;
        for (int d = tid; d < Dc; d += 256) {
            float a = row[d];
            const float* w = rW + d * Ec;
#pragma unroll
            for (int e = 0; e < Ec; e++) p[e] += a * w[e];
        }
    } else if (bid == Dc) {
        for (int d = tid; d < Dc; d += 256) {
            float a = qW[d];
            const float* w = rW + d * Ec;
#pragma unroll
            for (int e = 0; e < Ec; e++) p[e] += a * w[e];
        }
    } else {
        for (int d = tid; d < Dc; d += 256) {
            float a = ctx_b[d] + q_b[d];
            const float* w = rW + d * Ec;
#pragma unroll
            for (int e = 0; e < Ec; e++) p[e] += a * w[e];
        }
    }

    __shared__ float red[8][Ec];
#pragma unroll
    for (int e = 0; e < Ec; e++) {
        float v = p[e];
        for (int o = 16; o > 0; o >>= 1) v += __shfl_down_sync(0xffffffffu, v, o);
        if (lane == 0) red[wid][e] = v;
    }
    __syncthreads();
    if (tid < Ec) {
        float s = 0.f;
#pragma unroll
        for (int w = 0; w < 8; w++) s += red[w][tid];
        if (bid < Dc)        g_M[bid * Ec + tid] = s;
        else if (bid == Dc)  g_v[tid] = s;
        else                 g_Kc[tid] = s + r_b[tid];
    }
}

// ---------------- router: LN + logits + top2 + aux + scatter ----------------
__global__ void k_router(const float* __restrict__ x,
                         const float* __restrict__ ctx,
                         const float* __restrict__ quality,
                         const float* __restrict__ rn_g,
                         const float* __restrict__ rn_b,
                         const float* __restrict__ cn_g,
                         const float* __restrict__ cn_b,
                         const float* __restrict__ rW,
                         const float* __restrict__ temp_p) {
    const int tid = threadIdx.x;
    const int wid = tid >> 5, lane = tid & 31;

    __shared__ float s_r[8][4];     // stats partials per warp
    __shared__ float s_stats[4];    // mux, rsx, muc, rsc
    __shared__ float s_pr[8][Ec];   // logits partials per warp
    __shared__ float s_p[Ec];

    const float invtemp = 1.f / fmaxf(temp_p[0], 0.25f);

    // per-thread constant LN params (thread owns d = tid*4 .. tid*4+3)
    const float4 gX = ((const float4*)rn_g)[tid];
    const float4 bX = ((const float4*)rn_b)[tid];
    const float4 gC = ((const float4*)cn_g)[tid];
    const float4 bC = ((const float4*)cn_b)[tid];

    double acc_p[Ec];
#pragma unroll
    for (int e = 0; e < Ec; e++) acc_p[e] = 0.0;
    double acc_z2 = 0.0, acc_ent = 0.0;

    for (int t = blockIdx.x; t < Tc; t += gridDim.x) {
        const float4 xv = ((const float4*)(x  + (size_t)t * Dc))[tid];
        const float4 cv = ((const float4*)(ctx + (size_t)t * Dc))[tid];

        float sx  = xv.x + xv.y + xv.z + xv.w;
        float sxx = xv.x*xv.x + xv.y*xv.y + xv.z*xv.z + xv.w*xv.w;
        float sc  = cv.x + cv.y + cv.z + cv.w;
        float scc = cv.x*cv.x + cv.y*cv.y + cv.z*cv.z + cv.w*cv.w;
        for (int o = 16; o > 0; o >>= 1) {
            sx  += __shfl_down_sync(0xffffffffu, sx,  o);
            sxx += __shfl_down_sync(0xffffffffu, sxx, o);
            sc  += __shfl_down_sync(0xffffffffu, sc,  o);
            scc += __shfl_down_sync(0xffffffffu, scc, o);
        }
        if (lane == 0) { s_r[wid][0]=sx; s_r[wid][1]=sxx; s_r[wid][2]=sc; s_r[wid][3]=scc; }
        __syncthreads();
        if (tid == 0) {
            float a0=0,a1=0,a2=0,a3=0;
#pragma unroll
            for (int w = 0; w < 8; w++) { a0+=s_r[w][0]; a1+=s_r[w][1]; a2+=s_r[w][2]; a3+=s_r[w][3]; }
            float mux = a0 * (1.f/Dc);
            float varx = a1 * (1.f/Dc) - mux*mux;
            float muc = a2 * (1.f/Dc);
            float varc = a3 * (1.f/Dc) - muc*muc;
            s_stats[0]=mux; s_stats[1]=rsqrtf(varx + 1e-5f);
            s_stats[2]=muc; s_stats[3]=rsqrtf(varc + 1e-5f);
        }
        __syncthreads();
        const float mux=s_stats[0], rsx=s_stats[1], muc=s_stats[2], rsc=s_stats[3];

        float lnx[4], lnc[4];
        lnx[0]=(xv.x-mux)*rsx*gX.x+bX.x; lnx[1]=(xv.y-mux)*rsx*gX.y+bX.y;
        lnx[2]=(xv.z-mux)*rsx*gX.z+bX.z; lnx[3]=(xv.w-mux)*rsx*gX.w+bX.w;
        lnc[0]=(cv.x-muc)*rsc*gC.x+bC.x; lnc[1]=(cv.y-muc)*rsc*gC.y+bC.y;
        lnc[2]=(cv.z-muc)*rsc*gC.z+bC.z; lnc[3]=(cv.w-muc)*rsc*gC.w+bC.w;

        float p[Ec];
#pragma unroll
        for (int e = 0; e < Ec; e++) p[e] = 0.f;
        const int d0 = tid * 4;
#pragma unroll
        for (int j = 0; j < 4; j++) {
            const float* wr = rW  + (d0 + j) * Ec;
            const float* mr = g_M + (d0 + j) * Ec;
#pragma unroll
            for (int e = 0; e < Ec; e++) p[e] += lnx[j] * wr[e] + lnc[j] * mr[e];
        }
#pragma unroll
        for (int e = 0; e < Ec; e++) {
            float v = p[e];
            for (int o = 16; o > 0; o >>= 1) v += __shfl_down_sync(0xffffffffu, v, o);
            if (lane == 0) s_pr[wid][e] = v;
        }
        __syncthreads();

        if (tid == 0) {
            int b = t >> 11;   // S = 2048
            float q = quality[b];
            float l[Ec];
#pragma unroll
            for (int e = 0; e < Ec; e++) {
                float s = 0.f;
#pragma unroll
                for (int w = 0; w < 8; w++) s += s_pr[w][e];
                l[e] = (s + g_Kc[e] + q * g_v[e]) * invtemp;
            }
            // full softmax for aux
            float mx = l[0];
#pragma unroll
            for (int e = 1; e < Ec; e++) mx = fmaxf(mx, l[e]);
            float se = 0.f, pr[Ec];
#pragma unroll
            for (int e = 0; e < Ec; e++) { pr[e] = expf(l[e] - mx); se += pr[e]; }
            float lse = mx + logf(se);
            acc_z2 += (double)(lse * lse);
            float ent = 0.f;
            float inv_se = 1.f / se;
#pragma unroll
            for (int e = 0; e < Ec; e++) {
                pr[e] *= inv_se;
                acc_p[e] += (double)pr[e];
                ent -= pr[e] * logf(fmaxf(pr[e], 1e-9f));
            }
            acc_ent += (double)ent;

            // top-2 (lowest index wins ties, matching lax.top_k)
            int i1 = 0; float v1 = l[0];
#pragma unroll
            for (int e = 1; e < Ec; e++) if (l[e] > v1) { v1 = l[e]; i1 = e; }
            int i2 = (i1 == 0) ? 1 : 0; float v2 = l[i2];
#pragma unroll
            for (int e = 0; e < Ec; e++) if (e != i1 && l[e] > v2) { v2 = l[e]; i2 = e; }

            float e2 = expf(v2 - v1);
            float denom = 1.f / (1.f + e2);
            float g1 = denom, g2 = e2 * denom;
            g_gate[2*t]   = g1;
            g_gate[2*t+1] = g2;
            int p1 = atomicAdd(&g_cnt[i1], 1); g_slots[i1*Tc + p1] = 2*t;
            int p2 = atomicAdd(&g_cnt[i2], 1); g_slots[i2*Tc + p2] = 2*t + 1;
        }
        __syncthreads();
    }

    if (tid == 0) {
#pragma unroll
        for (int e = 0; e < Ec; e++) atomicAdd(&g_aux[e], acc_p[e]);
        atomicAdd(&g_aux[Ec],     acc_z2);
        atomicAdd(&g_aux[Ec + 1], acc_ent);
    }
}

// ---------------- grouped GEMM1: H = gelu(Xg @ W1[e] + b1[e]) ----------------
__global__ void __launch_bounds__(256, 2)
k_ffn1(const float* __restrict__ x,
       const float* __restrict__ W1,
       const float* __restrict__ b1) {
    const int e = blockIdx.z;
    const int cnt = g_cnt[e];
    const int m0 = blockIdx.y * 128;
    if (m0 >= cnt) return;
    const int n0 = blockIdx.x * 128;
    const float* W = W1 + (size_t)e * Dc * Hc;

    __shared__ float As[16][128];
    __shared__ float Bs[16][128];
    __shared__ int   rslot[128];
    __shared__ int   rtok[128];

    const int tid = threadIdx.x;
    if (tid < 128) {
        int m = m0 + tid;
        int slot = (m < cnt) ? g_slots[e*Tc + m] : 0;
        rslot[tid] = slot;
        rtok[tid]  = slot >> 1;
    }
    __syncthreads();

    float c[8][8];
#pragma unroll
    for (int i = 0; i < 8; i++)
#pragma unroll
        for (int j = 0; j < 8; j++) c[i][j] = 0.f;

    const int tr = tid >> 4, tc = tid & 15;

    for (int k0 = 0; k0 < Dc; k0 += 16) {
#pragma unroll
        for (int q = 0; q < 2; q++) {
            int lin = tid + q * 256;
            int row = lin >> 2, kq = lin & 3;
            const float4 v = *(const float4*)(x + (size_t)rtok[row] * Dc + k0 + kq * 4);
            As[kq*4+0][row] = v.x; As[kq*4+1][row] = v.y;
            As[kq*4+2][row] = v.z; As[kq*4+3][row] = v.w;
        }
#pragma unroll
        for (int q = 0; q < 2; q++) {
            int lin = tid + q * 256;
            int kr = lin >> 5, nq = lin & 31;
            *(float4*)&Bs[kr][nq*4] =
                *(const float4*)(W + (size_t)(k0 + kr) * Hc + n0 + nq * 4);
        }
        __syncthreads();
#pragma unroll
        for (int k = 0; k < 16; k++) {
            float a[8], bv[8];
#pragma unroll
            for (int i = 0; i < 8; i++) a[i]  = As[k][tr + 16*i];
#pragma unroll
            for (int j = 0; j < 8; j++) bv[j] = Bs[k][tc + 16*j];
#pragma unroll
            for (int i = 0; i < 8; i++)
#pragma unroll
                for (int j = 0; j < 8; j++) c[i][j] += a[i] * bv[j];
        }
        __syncthreads();
    }

#pragma unroll
    for (int i = 0; i < 8; i++) {
        int m = tr + 16 * i;
        if (m0 + m >= cnt) continue;
        float* dst = g_Hbuf + (size_t)rslot[m] * Hc + n0;
#pragma unroll
        for (int j = 0; j < 8; j++) {
            int n = tc + 16 * j;
            float h = c[i][j] + b1[e * Hc + n0 + n];
            dst[n] = 0.5f * h * (1.f + erff(h * 0.70710678118654752f));
        }
    }
}

// ---------------- grouped GEMM2: Y[slot] = gate * (Hg @ W2[e] + b2[e]) ----------------
__global__ void __launch_bounds__(256, 2)
k_ffn2(const float* __restrict__ W2,
       const float* __restrict__ b2) {
    const int e = blockIdx.z;
    const int cnt = g_cnt[e];
    const int m0 = blockIdx.y * 128;
    if (m0 >= cnt) return;
    const int n0 = blockIdx.x * 128;
    const float* W = W2 + (size_t)e * Hc * Dc;

    __shared__ float As[16][128];
    __shared__ float Bs[16][128];
    __shared__ int   rslot[128];
    __shared__ float rgate[128];

    const int tid = threadIdx.x;
    if (tid < 128) {
        int m = m0 + tid;
        int slot = (m < cnt) ? g_slots[e*Tc + m] : 0;
        rslot[tid] = slot;
        rgate[tid] = g_gate[slot];
    }
    __syncthreads();

    float c[8][8];
#pragma unroll
    for (int i = 0; i < 8; i++)
#pragma unroll
        for (int j = 0; j < 8; j++) c[i][j] = 0.f;

    const int tr = tid >> 4, tc = tid & 15;

    for (int k0 = 0; k0 < Hc; k0 += 16) {
#pragma unroll
        for (int q = 0; q < 2; q++) {
            int lin = tid + q * 256;
            int row = lin >> 2, kq = lin & 3;
            const float4 v = *(const float4*)(g_Hbuf + (size_t)rslot[row] * Hc + k0 + kq * 4);
            As[kq*4+0][row] = v.x; As[kq*4+1][row] = v.y;
            As[kq*4+2][row] = v.z; As[kq*4+3][row] = v.w;
        }
#pragma unroll
        for (int q = 0; q < 2; q++) {
            int lin = tid + q * 256;
            int kr = lin >> 5, nq = lin & 31;
            *(float4*)&Bs[kr][nq*4] =
                *(const float4*)(W + (size_t)(k0 + kr) * Dc + n0 + nq * 4);
        }
        __syncthreads();
#pragma unroll
        for (int k = 0; k < 16; k++) {
            float a[8], bv[8];
#pragma unroll
            for (int i = 0; i < 8; i++) a[i]  = As[k][tr + 16*i];
#pragma unroll
            for (int j = 0; j < 8; j++) bv[j] = Bs[k][tc + 16*j];
#pragma unroll
            for (int i = 0; i < 8; i++)
#pragma unroll
                for (int j = 0; j < 8; j++) c[i][j] += a[i] * bv[j];
        }
        __syncthreads();
    }

#pragma unroll
    for (int i = 0; i < 8; i++) {
        int m = tr + 16 * i;
        if (m0 + m >= cnt) continue;
        float g = rgate[m];
        float* dst = g_Ybuf + (size_t)rslot[m] * Dc + n0;
#pragma unroll
        for (int j = 0; j < 8; j++) {
            int n = tc + 16 * j;
            dst[n] = g * (c[i][j] + b2[e * Dc + n0 + n]);
        }
    }
}

// ---------------- combine the two slots per token ----------------
__global__ void k_combine(float* __restrict__ out) {
    size_t i = (size_t)blockIdx.x * blockDim.x + threadIdx.x;
    const size_t nvec = (size_t)Tc * Dc / 4;
    if (i >= nvec) return;
    const size_t dq_per = Dc / 4;
    size_t t = i / dq_per, dq = i % dq_per;
    const float4 a = ((const float4*)g_Ybuf)[(2*t)   * dq_per + dq];
    const float4 b = ((const float4*)g_Ybuf)[(2*t+1) * dq_per + dq];
    float4 r; r.x = a.x + b.x; r.y = a.y + b.y; r.z = a.z + b.z; r.w = a.w + b.w;
    ((float4*)out)[i] = r;
}

// ---------------- aux scalar losses ----------------
__global__ void k_scalars(float* __restrict__ out) {
    if (threadIdx.x == 0 && blockIdx.x == 0) {
        const double invT = 1.0 / (double)Tc;
        double lb = 0.0;
        for (int e = 0; e < Ec; e++) {
            double imp = g_aux[e] * invT;
            double d = imp - 1.0 / Ec;
            lb += d * d;
        }
        lb /= Ec;
        double rz  = g_aux[Ec]     * invT;
        double ent = g_aux[Ec + 1] * invT;
        out[(size_t)Tc*Dc + 0] = (float)lb;
        out[(size_t)Tc*Dc + 1] = (float)rz;
        out[(size_t)Tc*Dc + 2] = (float)ent;
        out[(size_t)Tc*Dc + 3] = (float)(lb + 0.001 * rz - 0.001 * ent);
    }
}

// ---------------- launch ----------------
extern "C" void kernel_launch(void* const* d_in, const int* in_sizes, int n_in,
                              void* d_out, int out_size) {
    const float* x       = (const float*)d_in[0];
    const float* context = (const float*)d_in[1];
    const float* quality = (const float*)d_in[2];
    const float* rn_g    = (const float*)d_in[3];
    const float* rn_b    = (const float*)d_in[4];
    const float* cn_g    = (const float*)d_in[5];
    const float* cn_b    = (const float*)d_in[6];
    const float* ctx_W   = (const float*)d_in[7];
    const float* ctx_b   = (const float*)d_in[8];
    const float* q_W     = (const float*)d_in[9];
    const float* q_b     = (const float*)d_in[10];
    const float* r_W     = (const float*)d_in[11];
    const float* r_b     = (const float*)d_in[12];
    const float* temp_p  = (const float*)d_in[13];
    const float* W1      = (const float*)d_in[14];
    const float* b1      = (const float*)d_in[15];
    const float* W2      = (const float*)d_in[16];
    const float* b2      = (const float*)d_in[17];
    float* out = (float*)d_out;

    k_init<<<1, 32>>>();
    k_prep<<<Dc + 2, 256>>>(ctx_W, r_W, q_W, ctx_b, q_b, r_b);
    k_router<<<296, 256>>>(x, context, quality, rn_g, rn_b, cn_g, cn_b, r_W, temp_p);

    dim3 g1(Hc / 128, Tc / 128, Ec);   // 32 x 64 x 8
    k_ffn1<<<g1, 256>>>(x, W1, b1);

    dim3 g2(Dc / 128, Tc / 128, Ec);   // 8 x 64 x 8
    k_ffn2<<<g2, 256>>>(W2, b2);

    const size_t nvec = (size_t)Tc * Dc / 4;
    k_combine<<<(unsigned)((nvec + 255) / 256), 256>>>(out);
    k_scalars<<<1, 32>>>(out);
}

// round 9
// speedup vs baseline: 1.3631x; 1.3631x over previous
#include <cuda_runtime.h>
#include <math.h>
#include <stdint.h>

// Problem constants
#define Bc 4
#define Sc 2048
#define Dc 1024
#define Hc 4096
#define Ec 8
#define Tc (Bc*Sc)          // 8192 tokens
#define NSLOT (2*Tc)        // 16384 (token, k) slots

// ---------------- device scratch (static, no allocs) ----------------
__device__ float  g_M[Dc*Ec];
__device__ float  g_v[Ec];
__device__ float  g_Kc[Ec];
__device__ int    g_cnt[Ec];
__device__ int    g_slots[Ec*Tc];
__device__ float  g_gate[NSLOT];
__device__ double g_aux[Ec + 2];
__device__ float  g_Hbuf[(size_t)NSLOT * Hc]; // 256 MiB intermediate
__device__ float  g_Ybuf[(size_t)NSLOT * Dc]; // 64 MiB per-slot outputs

// ---------------- f32x2 packed helpers ----------------
__device__ __forceinline__ void fma_x2(unsigned long long& d,
                                       unsigned long long a,
                                       unsigned long long b) {
    asm("fma.rn.f32x2 %0, %1, %2, %0;" : "+l"(d) : "l"(a), "l"(b));
}
__device__ __forceinline__ unsigned long long pack_dup(float a) {
    unsigned long long d;
    asm("mov.b64 %0, {%1, %1};" : "=l"(d) : "f"(a));
    return d;
}
__device__ __forceinline__ void unpack_x2(float& lo, float& hi, unsigned long long v) {
    asm("mov.b64 {%0, %1}, %2;" : "=f"(lo), "=f"(hi) : "l"(v));
}

// ---------------- init ----------------
__global__ void k_init() {
    int i = threadIdx.x;
    if (i < Ec) g_cnt[i] = 0;
    if (i < Ec + 2) g_aux[i] = 0.0;
}

// ---------------- router precompute: M, v, Kc ----------------
__global__ void k_prep(const float* __restrict__ ctxW,
                       const float* __restrict__ rW,
                       const float* __restrict__ qW,
                       const float* __restrict__ ctx_b,
                       const float* __restrict__ q_b,
                       const float* __restrict__ r_b) {
    int bid = blockIdx.x, tid = threadIdx.x;
    int wid = tid >> 5, lane = tid & 31;
    float p[Ec];
#pragma unroll
    for (int e = 0; e < Ec; e++) p[e] = 0.f;

    if (bid < Dc) {
        const float* row = ctxW + (size_t)bid * Dc;
        for (int d = tid; d < Dc; d += 256) {
            float a = row[d];
            const float* w = rW + d * Ec;
#pragma unroll
            for (int e = 0; e < Ec; e++) p[e] += a * w[e];
        }
    } else if (bid == Dc) {
        for (int d = tid; d < Dc; d += 256) {
            float a = qW[d];
            const float* w = rW + d * Ec;
#pragma unroll
            for (int e = 0; e < Ec; e++) p[e] += a * w[e];
        }
    } else {
        for (int d = tid; d < Dc; d += 256) {
            float a = ctx_b[d] + q_b[d];
            const float* w = rW + d * Ec;
#pragma unroll
            for (int e = 0; e < Ec; e++) p[e] += a * w[e];
        }
    }

    __shared__ float red[8][Ec];
#pragma unroll
    for (int e = 0; e < Ec; e++) {
        float v = p[e];
        for (int o = 16; o > 0; o >>= 1) v += __shfl_down_sync(0xffffffffu, v, o);
        if (lane == 0) red[wid][e] = v;
    }
    __syncthreads();
    if (tid < Ec) {
        float s = 0.f;
#pragma unroll
        for (int w = 0; w < 8; w++) s += red[w][tid];
        if (bid < Dc)        g_M[bid * Ec + tid] = s;
        else if (bid == Dc)  g_v[tid] = s;
        else                 g_Kc[tid] = s + r_b[tid];
    }
}

// ---------------- router: LN + logits + top2 + aux + scatter ----------------
__global__ void k_router(const float* __restrict__ x,
                         const float* __restrict__ ctx,
                         const float* __restrict__ quality,
                         const float* __restrict__ rn_g,
                         const float* __restrict__ rn_b,
                         const float* __restrict__ cn_g,
                         const float* __restrict__ cn_b,
                         const float* __restrict__ rW,
                         const float* __restrict__ temp_p) {
    const int tid = threadIdx.x;
    const int wid = tid >> 5, lane = tid & 31;

    __shared__ float s_r[8][4];
    __shared__ float s_stats[4];
    __shared__ float s_pr[8][Ec];

    const float invtemp = 1.f / fmaxf(temp_p[0], 0.25f);

    const float4 gX = ((const float4*)rn_g)[tid];
    const float4 bX = ((const float4*)rn_b)[tid];
    const float4 gC = ((const float4*)cn_g)[tid];
    const float4 bC = ((const float4*)cn_b)[tid];

    double acc_p[Ec];
#pragma unroll
    for (int e = 0; e < Ec; e++) acc_p[e] = 0.0;
    double acc_z2 = 0.0, acc_ent = 0.0;

    for (int t = blockIdx.x; t < Tc; t += gridDim.x) {
        const float4 xv = ((const float4*)(x  + (size_t)t * Dc))[tid];
        const float4 cv = ((const float4*)(ctx + (size_t)t * Dc))[tid];

        float sx  = xv.x + xv.y + xv.z + xv.w;
        float sxx = xv.x*xv.x + xv.y*xv.y + xv.z*xv.z + xv.w*xv.w;
        float sc  = cv.x + cv.y + cv.z + cv.w;
        float scc = cv.x*cv.x + cv.y*cv.y + cv.z*cv.z + cv.w*cv.w;
        for (int o = 16; o > 0; o >>= 1) {
            sx  += __shfl_down_sync(0xffffffffu, sx,  o);
            sxx += __shfl_down_sync(0xffffffffu, sxx, o);
            sc  += __shfl_down_sync(0xffffffffu, sc,  o);
            scc += __shfl_down_sync(0xffffffffu, scc, o);
        }
        if (lane == 0) { s_r[wid][0]=sx; s_r[wid][1]=sxx; s_r[wid][2]=sc; s_r[wid][3]=scc; }
        __syncthreads();
        if (tid == 0) {
            float a0=0,a1=0,a2=0,a3=0;
#pragma unroll
            for (int w = 0; w < 8; w++) { a0+=s_r[w][0]; a1+=s_r[w][1]; a2+=s_r[w][2]; a3+=s_r[w][3]; }
            float mux = a0 * (1.f/Dc);
            float varx = a1 * (1.f/Dc) - mux*mux;
            float muc = a2 * (1.f/Dc);
            float varc = a3 * (1.f/Dc) - muc*muc;
            s_stats[0]=mux; s_stats[1]=rsqrtf(varx + 1e-5f);
            s_stats[2]=muc; s_stats[3]=rsqrtf(varc + 1e-5f);
        }
        __syncthreads();
        const float mux=s_stats[0], rsx=s_stats[1], muc=s_stats[2], rsc=s_stats[3];

        float lnx[4], lnc[4];
        lnx[0]=(xv.x-mux)*rsx*gX.x+bX.x; lnx[1]=(xv.y-mux)*rsx*gX.y+bX.y;
        lnx[2]=(xv.z-mux)*rsx*gX.z+bX.z; lnx[3]=(xv.w-mux)*rsx*gX.w+bX.w;
        lnc[0]=(cv.x-muc)*rsc*gC.x+bC.x; lnc[1]=(cv.y-muc)*rsc*gC.y+bC.y;
        lnc[2]=(cv.z-muc)*rsc*gC.z+bC.z; lnc[3]=(cv.w-muc)*rsc*gC.w+bC.w;

        float p[Ec];
#pragma unroll
        for (int e = 0; e < Ec; e++) p[e] = 0.f;
        const int d0 = tid * 4;
#pragma unroll
        for (int j = 0; j < 4; j++) {
            const float* wr = rW  + (d0 + j) * Ec;
            const float* mr = g_M + (d0 + j) * Ec;
#pragma unroll
            for (int e = 0; e < Ec; e++) p[e] += lnx[j] * wr[e] + lnc[j] * mr[e];
        }
#pragma unroll
        for (int e = 0; e < Ec; e++) {
            float v = p[e];
            for (int o = 16; o > 0; o >>= 1) v += __shfl_down_sync(0xffffffffu, v, o);
            if (lane == 0) s_pr[wid][e] = v;
        }
        __syncthreads();

        if (tid == 0) {
            int b = t >> 11;   // S = 2048
            float q = quality[b];
            float l[Ec];
#pragma unroll
            for (int e = 0; e < Ec; e++) {
                float s = 0.f;
#pragma unroll
                for (int w = 0; w < 8; w++) s += s_pr[w][e];
                l[e] = (s + g_Kc[e] + q * g_v[e]) * invtemp;
            }
            float mx = l[0];
#pragma unroll
            for (int e = 1; e < Ec; e++) mx = fmaxf(mx, l[e]);
            float se = 0.f, pr[Ec];
#pragma unroll
            for (int e = 0; e < Ec; e++) { pr[e] = expf(l[e] - mx); se += pr[e]; }
            float lse = mx + logf(se);
            acc_z2 += (double)(lse * lse);
            float ent = 0.f;
            float inv_se = 1.f / se;
#pragma unroll
            for (int e = 0; e < Ec; e++) {
                pr[e] *= inv_se;
                acc_p[e] += (double)pr[e];
                ent -= pr[e] * logf(fmaxf(pr[e], 1e-9f));
            }
            acc_ent += (double)ent;

            int i1 = 0; float v1 = l[0];
#pragma unroll
            for (int e = 1; e < Ec; e++) if (l[e] > v1) { v1 = l[e]; i1 = e; }
            int i2 = (i1 == 0) ? 1 : 0; float v2 = l[i2];
#pragma unroll
            for (int e = 0; e < Ec; e++) if (e != i1 && l[e] > v2) { v2 = l[e]; i2 = e; }

            float e2 = expf(v2 - v1);
            float denom = 1.f / (1.f + e2);
            g_gate[2*t]   = denom;
            g_gate[2*t+1] = e2 * denom;
            int p1 = atomicAdd(&g_cnt[i1], 1); g_slots[i1*Tc + p1] = 2*t;
            int p2 = atomicAdd(&g_cnt[i2], 1); g_slots[i2*Tc + p2] = 2*t + 1;
        }
        __syncthreads();
    }

    if (tid == 0) {
#pragma unroll
        for (int e = 0; e < Ec; e++) atomicAdd(&g_aux[e], acc_p[e]);
        atomicAdd(&g_aux[Ec],     acc_z2);
        atomicAdd(&g_aux[Ec + 1], acc_ent);
    }
}

// ---------------- grouped GEMM: fp32, packed f32x2 FMA, double-buffered ----------------
// NOTE: all __device__ global buffers are selected INSIDE the kernel (template
// bool) — never passed from host code (that was the R3-R6 root-cause bug).
template<bool IS_FFN1, int KTOT, int NTOT>
__global__ void __launch_bounds__(256, 2)
k_ffn(const float* __restrict__ Ain,      // x for FFN1; ignored for FFN2
      const float* __restrict__ Wg,       // W1 / W2 (harness pointers)
      const float* __restrict__ bias) {
    constexpr int NC = KTOT / 16;
    __shared__ float As[2][16][132];   // padded rows
    __shared__ float Bs[2][16][128];
    __shared__ int   rslot[128];
    __shared__ float rgate[128];
    __shared__ int   rrow[128];

    const float* Aglob = IS_FFN1 ? Ain : (const float*)g_Hbuf;
    float*       Obuf  = IS_FFN1 ? g_Hbuf : g_Ybuf;

    const int e = blockIdx.z;
    const int cnt = g_cnt[e];
    const int m0 = blockIdx.y * 128;
    if (m0 >= cnt) return;
    const int n0 = blockIdx.x * 128;
    const float* W = Wg + (size_t)e * KTOT * NTOT;
    const int tid = threadIdx.x;

    if (tid < 128) {
        int m = m0 + tid;
        int slot = (m < cnt) ? g_slots[e * Tc + m] : g_slots[e * Tc + cnt - 1];
        rslot[tid] = slot;
        rgate[tid] = g_gate[slot];
        rrow[tid]  = IS_FFN1 ? (slot >> 1) : slot;
    }
    __syncthreads();

    // loader addressing
    const int lrow = tid >> 2;            // 0..63
    const int lkq  = (tid & 3) * 4;       // k offset 0/4/8/12
    const float* pa0 = Aglob + (size_t)rrow[lrow]      * KTOT + lkq;
    const float* pa1 = Aglob + (size_t)rrow[64 + lrow] * KTOT + lkq;
    const int bkr = tid >> 5;             // 0..7
    const int bnq = (tid & 31) * 4;
    const float* pb0 = W + (size_t)bkr       * NTOT + n0 + bnq;
    const float* pb1 = W + (size_t)(8 + bkr) * NTOT + n0 + bnq;

    const int tx = tid & 15, ty = tid >> 4;

    unsigned long long acc[8][4];
#pragma unroll
    for (int i = 0; i < 8; i++)
#pragma unroll
        for (int j = 0; j < 4; j++) acc[i][j] = 0ull;

    // prologue: chunk 0 -> buf 0
    {
        float4 rA0 = *(const float4*)pa0;
        float4 rA1 = *(const float4*)pa1;
        float4 rB0 = *(const float4*)pb0;
        float4 rB1 = *(const float4*)pb1;
        As[0][lkq+0][lrow] = rA0.x; As[0][lkq+1][lrow] = rA0.y;
        As[0][lkq+2][lrow] = rA0.z; As[0][lkq+3][lrow] = rA0.w;
        As[0][lkq+0][64+lrow] = rA1.x; As[0][lkq+1][64+lrow] = rA1.y;
        As[0][lkq+2][64+lrow] = rA1.z; As[0][lkq+3][64+lrow] = rA1.w;
        *(float4*)&Bs[0][bkr][bnq]     = rB0;
        *(float4*)&Bs[0][8+bkr][bnq]   = rB1;
    }
    __syncthreads();

    for (int c = 0; c < NC; c++) {
        const int cur = c & 1;
        float4 rA0, rA1, rB0, rB1;
        if (c + 1 < NC) {
            const int k0 = (c + 1) * 16;
            rA0 = *(const float4*)(pa0 + k0);
            rA1 = *(const float4*)(pa1 + k0);
            rB0 = *(const float4*)(pb0 + (size_t)k0 * NTOT);
            rB1 = *(const float4*)(pb1 + (size_t)k0 * NTOT);
        }

#pragma unroll
        for (int k = 0; k < 16; k++) {
            float4 a0 = *(const float4*)&As[cur][k][ty * 4];
            float4 a1 = *(const float4*)&As[cur][k][64 + ty * 4];
            ulonglong2 b0 = *(const ulonglong2*)&Bs[cur][k][tx * 4];
            ulonglong2 b1 = *(const ulonglong2*)&Bs[cur][k][64 + tx * 4];
            unsigned long long a2[8];
            a2[0] = pack_dup(a0.x); a2[1] = pack_dup(a0.y);
            a2[2] = pack_dup(a0.z); a2[3] = pack_dup(a0.w);
            a2[4] = pack_dup(a1.x); a2[5] = pack_dup(a1.y);
            a2[6] = pack_dup(a1.z); a2[7] = pack_dup(a1.w);
#pragma unroll
            for (int i = 0; i < 8; i++) {
                fma_x2(acc[i][0], a2[i], b0.x);
                fma_x2(acc[i][1], a2[i], b0.y);
                fma_x2(acc[i][2], a2[i], b1.x);
                fma_x2(acc[i][3], a2[i], b1.y);
            }
        }

        if (c + 1 < NC) {
            const int nxt = cur ^ 1;
            __syncthreads();   // ensure all warps done reading buf nxt from 2 chunks ago
            As[nxt][lkq+0][lrow] = rA0.x; As[nxt][lkq+1][lrow] = rA0.y;
            As[nxt][lkq+2][lrow] = rA0.z; As[nxt][lkq+3][lrow] = rA0.w;
            As[nxt][lkq+0][64+lrow] = rA1.x; As[nxt][lkq+1][64+lrow] = rA1.y;
            As[nxt][lkq+2][64+lrow] = rA1.z; As[nxt][lkq+3][64+lrow] = rA1.w;
            *(float4*)&Bs[nxt][bkr][bnq]   = rB0;
            *(float4*)&Bs[nxt][8+bkr][bnq] = rB1;
            __syncthreads();
        }
    }

    // ---------------- epilogue ----------------
    const float* brow = bias + (size_t)e * NTOT + n0;
#pragma unroll
    for (int i = 0; i < 8; i++) {
        const int r = (i < 4) ? (ty * 4 + i) : (64 + ty * 4 + (i - 4));
        if (m0 + r >= cnt) continue;
        const int slot = rslot[r];
        const float gate = rgate[r];
        float* dst = Obuf + (size_t)slot * NTOT + n0;
#pragma unroll
        for (int j2 = 0; j2 < 4; j2++) {
            const int col = (j2 < 2) ? (tx * 4 + j2 * 2) : (64 + tx * 4 + (j2 - 2) * 2);
            float v0, v1;
            unpack_x2(v0, v1, acc[i][j2]);
            float2 bv = *(const float2*)(brow + col);
            v0 += bv.x; v1 += bv.y;
            float2 o;
            if (IS_FFN1) {
                o.x = 0.5f * v0 * (1.f + erff(v0 * 0.70710678118654752f));
                o.y = 0.5f * v1 * (1.f + erff(v1 * 0.70710678118654752f));
            } else {
                o.x = gate * v0;
                o.y = gate * v1;
            }
            *(float2*)(dst + col) = o;
        }
    }
}

// ---------------- combine the two slots per token ----------------
__global__ void k_combine(float* __restrict__ out) {
    size_t i = (size_t)blockIdx.x * blockDim.x + threadIdx.x;
    const size_t nvec = (size_t)Tc * Dc / 4;
    if (i >= nvec) return;
    const size_t dq_per = Dc / 4;
    size_t t = i / dq_per, dq = i % dq_per;
    const float4 a = ((const float4*)g_Ybuf)[(2*t)   * dq_per + dq];
    const float4 b = ((const float4*)g_Ybuf)[(2*t+1) * dq_per + dq];
    float4 r; r.x = a.x + b.x; r.y = a.y + b.y; r.z = a.z + b.z; r.w = a.w + b.w;
    ((float4*)out)[i] = r;
}

// ---------------- aux scalar losses ----------------
__global__ void k_scalars(float* __restrict__ out) {
    if (threadIdx.x == 0 && blockIdx.x == 0) {
        const double invT = 1.0 / (double)Tc;
        double lb = 0.0;
        for (int e = 0; e < Ec; e++) {
            double imp = g_aux[e] * invT;
            double d = imp - 1.0 / Ec;
            lb += d * d;
        }
        lb /= Ec;
        double rz  = g_aux[Ec]     * invT;
        double ent = g_aux[Ec + 1] * invT;
        out[(size_t)Tc*Dc + 0] = (float)lb;
        out[(size_t)Tc*Dc + 1] = (float)rz;
        out[(size_t)Tc*Dc + 2] = (float)ent;
        out[(size_t)Tc*Dc + 3] = (float)(lb + 0.001 * rz - 0.001 * ent);
    }
}

// ---------------- launch ----------------
extern "C" void kernel_launch(void* const* d_in, const int* in_sizes, int n_in,
                              void* d_out, int out_size) {
    const float* x       = (const float*)d_in[0];
    const float* context = (const float*)d_in[1];
    const float* quality = (const float*)d_in[2];
    const float* rn_g    = (const float*)d_in[3];
    const float* rn_b    = (const float*)d_in[4];
    const float* cn_g    = (const float*)d_in[5];
    const float* cn_b    = (const float*)d_in[6];
    const float* ctx_W   = (const float*)d_in[7];
    const float* ctx_b   = (const float*)d_in[8];
    const float* q_W     = (const float*)d_in[9];
    const float* q_b     = (const float*)d_in[10];
    const float* r_W     = (const float*)d_in[11];
    const float* r_b     = (const float*)d_in[12];
    const float* temp_p  = (const float*)d_in[13];
    const float* W1      = (const float*)d_in[14];
    const float* b1      = (const float*)d_in[15];
    const float* W2      = (const float*)d_in[16];
    const float* b2      = (const float*)d_in[17];
    float* out = (float*)d_out;

    k_init<<<1, 32>>>();
    k_prep<<<Dc + 2, 256>>>(ctx_W, r_W, q_W, ctx_b, q_b, r_b);
    k_router<<<296, 256>>>(x, context, quality, rn_g, rn_b, cn_g, cn_b, r_W, temp_p);

    dim3 g1(Hc / 128, Tc / 128, Ec);   // 32 x 64 x 8
    k_ffn<true,  Dc, Hc><<<g1, 256>>>(x, W1, b1);

    dim3 g2(Dc / 128, Tc / 128, Ec);   // 8 x 64 x 8
    k_ffn<false, Hc, Dc><<<g2, 256>>>(nullptr, W2, b2);

    const size_t nvec = (size_t)Tc * Dc / 4;
    k_combine<<<(unsigned)((nvec + 255) / 256), 256>>>(out);
    k_scalars<<<1, 32>>>(out);
}

// round 14
// speedup vs baseline: 2.1480x; 1.5758x over previous
#include <cuda_runtime.h>
#include <cuda_fp16.h>
#include <mma.h>
#include <math.h>
#include <stdint.h>

using namespace nvcuda;

// Problem constants
#define Bc 4
#define Sc 2048
#define Dc 1024
#define Hc 4096
#define Ec 8
#define Tc (Bc*Sc)          // 8192 tokens
#define NSLOT (2*Tc)        // 16384 (token, k) slots

// SMEM layout for k_ffn (dynamic)
#define A_LD 40             // halves per A row (32 + 8 pad); 80B stride
#define B_LD 136            // halves per B row (128 + 8 pad); 272B stride
#define C_LDM 136           // floats per C staging row
#define OFF_AH   2048
#define OFF_AL   12288
#define OFF_BH   22528
#define OFF_BL   31232
#define SM_TOTAL 39936      // < 48KB, no opt-in needed

// ---------------- device scratch (static, no allocs) ----------------
// RULE (R3-R6 root cause): __device__ symbols are ONLY referenced inside
// device code, never passed as kernel arguments from host code.
__device__ float  g_M[Dc*Ec];
__device__ float  g_v[Ec];
__device__ float  g_Kc[Ec];
__device__ int    g_cnt[Ec];
__device__ int    g_slots[Ec*Tc];
__device__ float  g_gate[NSLOT];
__device__ double g_aux[Ec + 2];
__device__ float  g_Hbuf[(size_t)NSLOT * Hc]; // 256 MiB intermediate
__device__ float  g_Ybuf[(size_t)NSLOT * Dc]; // 64 MiB per-slot outputs

// ---------------- init ----------------
__global__ void k_init() {
    int i = threadIdx.x;
    if (i < Ec) g_cnt[i] = 0;
    if (i < Ec + 2) g_aux[i] = 0.0;
}

// ---------------- router precompute: M, v, Kc ----------------
__global__ void k_prep(const float* __restrict__ ctxW,
                       const float* __restrict__ rW,
                       const float* __restrict__ qW,
                       const float* __restrict__ ctx_b,
                       const float* __restrict__ q_b,
                       const float* __restrict__ r_b) {
    int bid = blockIdx.x, tid = threadIdx.x;
    int wid = tid >> 5, lane = tid & 31;
    float p[Ec];
#pragma unroll
    for (int e = 0; e < Ec; e++) p[e] = 0.f;

    if (bid < Dc) {
        const float* row = ctxW + (size_t)bid * Dc;
        for (int d = tid; d < Dc; d += 256) {
            float a = row[d];
            const float* w = rW + d * Ec;
#pragma unroll
            for (int e = 0; e < Ec; e++) p[e] += a * w[e];
        }
    } else if (bid == Dc) {
        for (int d = tid; d < Dc; d += 256) {
            float a = qW[d];
            const float* w = rW + d * Ec;
#pragma unroll
            for (int e = 0; e < Ec; e++) p[e] += a * w[e];
        }
    } else {
        for (int d = tid; d < Dc; d += 256) {
            float a = ctx_b[d] + q_b[d];
            const float* w = rW + d * Ec;
#pragma unroll
            for (int e = 0; e < Ec; e++) p[e] += a * w[e];
        }
    }

    __shared__ float red[8][Ec];
#pragma unroll
    for (int e = 0; e < Ec; e++) {
        float v = p[e];
        for (int o = 16; o > 0; o >>= 1) v += __shfl_down_sync(0xffffffffu, v, o);
        if (lane == 0) red[wid][e] = v;
    }
    __syncthreads();
    if (tid < Ec) {
        float s = 0.f;
#pragma unroll
        for (int w = 0; w < 8; w++) s += red[w][tid];
        if (bid < Dc)        g_M[bid * Ec + tid] = s;
        else if (bid == Dc)  g_v[tid] = s;
        else                 g_Kc[tid] = s + r_b[tid];
    }
}

// ---------------- router: LN + logits + top2 + aux + scatter ----------------
__global__ void k_router(const float* __restrict__ x,
                         const float* __restrict__ ctx,
                         const float* __restrict__ quality,
                         const float* __restrict__ rn_g,
                         const float* __restrict__ rn_b,
                         const float* __restrict__ cn_g,
                         const float* __restrict__ cn_b,
                         const float* __restrict__ rW,
                         const float* __restrict__ temp_p) {
    const int tid = threadIdx.x;
    const int wid = tid >> 5, lane = tid & 31;

    __shared__ float s_r[8][4];
    __shared__ float s_stats[4];
    __shared__ float s_pr[8][Ec];

    const float invtemp = 1.f / fmaxf(temp_p[0], 0.25f);

    const float4 gX = ((const float4*)rn_g)[tid];
    const float4 bX = ((const float4*)rn_b)[tid];
    const float4 gC = ((const float4*)cn_g)[tid];
    const float4 bC = ((const float4*)cn_b)[tid];

    double acc_p[Ec];
#pragma unroll
    for (int e = 0; e < Ec; e++) acc_p[e] = 0.0;
    double acc_z2 = 0.0, acc_ent = 0.0;

    for (int t = blockIdx.x; t < Tc; t += gridDim.x) {
        const float4 xv = ((const float4*)(x  + (size_t)t * Dc))[tid];
        const float4 cv = ((const float4*)(ctx + (size_t)t * Dc))[tid];

        float sx  = xv.x + xv.y + xv.z + xv.w;
        float sxx = xv.x*xv.x + xv.y*xv.y + xv.z*xv.z + xv.w*xv.w;
        float sc  = cv.x + cv.y + cv.z + cv.w;
        float scc = cv.x*cv.x + cv.y*cv.y + cv.z*cv.z + cv.w*cv.w;
        for (int o = 16; o > 0; o >>= 1) {
            sx  += __shfl_down_sync(0xffffffffu, sx,  o);
            sxx += __shfl_down_sync(0xffffffffu, sxx, o);
            sc  += __shfl_down_sync(0xffffffffu, sc,  o);
            scc += __shfl_down_sync(0xffffffffu, scc, o);
        }
        if (lane == 0) { s_r[wid][0]=sx; s_r[wid][1]=sxx; s_r[wid][2]=sc; s_r[wid][3]=scc; }
        __syncthreads();
        if (tid == 0) {
            float a0=0,a1=0,a2=0,a3=0;
#pragma unroll
            for (int w = 0; w < 8; w++) { a0+=s_r[w][0]; a1+=s_r[w][1]; a2+=s_r[w][2]; a3+=s_r[w][3]; }
            float mux = a0 * (1.f/Dc);
            float varx = a1 * (1.f/Dc) - mux*mux;
            float muc = a2 * (1.f/Dc);
            float varc = a3 * (1.f/Dc) - muc*muc;
            s_stats[0]=mux; s_stats[1]=rsqrtf(varx + 1e-5f);
            s_stats[2]=muc; s_stats[3]=rsqrtf(varc + 1e-5f);
        }
        __syncthreads();
        const float mux=s_stats[0], rsx=s_stats[1], muc=s_stats[2], rsc=s_stats[3];

        float lnx[4], lnc[4];
        lnx[0]=(xv.x-mux)*rsx*gX.x+bX.x; lnx[1]=(xv.y-mux)*rsx*gX.y+bX.y;
        lnx[2]=(xv.z-mux)*rsx*gX.z+bX.z; lnx[3]=(xv.w-mux)*rsx*gX.w+bX.w;
        lnc[0]=(cv.x-muc)*rsc*gC.x+bC.x; lnc[1]=(cv.y-muc)*rsc*gC.y+bC.y;
        lnc[2]=(cv.z-muc)*rsc*gC.z+bC.z; lnc[3]=(cv.w-muc)*rsc*gC.w+bC.w;

        float p[Ec];
#pragma unroll
        for (int e = 0; e < Ec; e++) p[e] = 0.f;
        const int d0 = tid * 4;
#pragma unroll
        for (int j = 0; j < 4; j++) {
            const float* wr = rW  + (d0 + j) * Ec;
            const float* mr = g_M + (d0 + j) * Ec;
#pragma unroll
            for (int e = 0; e < Ec; e++) p[e] += lnx[j] * wr[e] + lnc[j] * mr[e];
        }
#pragma unroll
        for (int e = 0; e < Ec; e++) {
            float v = p[e];
            for (int o = 16; o > 0; o >>= 1) v += __shfl_down_sync(0xffffffffu, v, o);
            if (lane == 0) s_pr[wid][e] = v;
        }
        __syncthreads();

        if (tid == 0) {
            int b = t >> 11;   // S = 2048
            float q = quality[b];
            float l[Ec];
#pragma unroll
            for (int e = 0; e < Ec; e++) {
                float s = 0.f;
#pragma unroll
                for (int w = 0; w < 8; w++) s += s_pr[w][e];
                l[e] = (s + g_Kc[e] + q * g_v[e]) * invtemp;
            }
            float mx = l[0];
#pragma unroll
            for (int e = 1; e < Ec; e++) mx = fmaxf(mx, l[e]);
            float se = 0.f, pr[Ec];
#pragma unroll
            for (int e = 0; e < Ec; e++) { pr[e] = expf(l[e] - mx); se += pr[e]; }
            float lse = mx + logf(se);
            acc_z2 += (double)(lse * lse);
            float ent = 0.f;
            float inv_se = 1.f / se;
#pragma unroll
            for (int e = 0; e < Ec; e++) {
                pr[e] *= inv_se;
                acc_p[e] += (double)pr[e];
                ent -= pr[e] * logf(fmaxf(pr[e], 1e-9f));
            }
            acc_ent += (double)ent;

            int i1 = 0; float v1 = l[0];
#pragma unroll
            for (int e = 1; e < Ec; e++) if (l[e] > v1) { v1 = l[e]; i1 = e; }
            int i2 = (i1 == 0) ? 1 : 0; float v2 = l[i2];
#pragma unroll
            for (int e = 0; e < Ec; e++) if (e != i1 && l[e] > v2) { v2 = l[e]; i2 = e; }

            float e2 = expf(v2 - v1);
            float denom = 1.f / (1.f + e2);
            g_gate[2*t]   = denom;
            g_gate[2*t+1] = e2 * denom;
            int p1 = atomicAdd(&g_cnt[i1], 1); g_slots[i1*Tc + p1] = 2*t;
            int p2 = atomicAdd(&g_cnt[i2], 1); g_slots[i2*Tc + p2] = 2*t + 1;
        }
        __syncthreads();
    }

    if (tid == 0) {
#pragma unroll
        for (int e = 0; e < Ec; e++) atomicAdd(&g_aux[e], acc_p[e]);
        atomicAdd(&g_aux[Ec],     acc_z2);
        atomicAdd(&g_aux[Ec + 1], acc_ent);
    }
}

// ---------------- grouped GEMM via wmma: 3-pass fp16 hi/lo split ----------------
// CTA 128x128, k-chunk 32. 8 warps in 2x4 grid of 64x32 warp tiles.
// A (fp32 gathered rows) and W (fp32, row-major KxN) are converted to fp16
// hi/lo IN SMEM each chunk. Passes: Ah*Bh + Al*Bh + Ah*Bl (residual ~2^-22).
// Global buffers selected INSIDE the kernel via template bool.
template<bool IS_FFN1, int KTOT, int NTOT>
__global__ void __launch_bounds__(256, 2)
k_ffn(const float* __restrict__ Ain,      // x for FFN1; ignored for FFN2
      const float* __restrict__ Wg,       // harness W1 / W2 pointer
      const float* __restrict__ bias) {
    constexpr int NC = KTOT / 32;
    extern __shared__ char dsm[];
    int*    rslot = (int*)dsm;
    float*  rgate = (float*)(dsm + 512);
    int*    rrow  = (int*)(dsm + 1024);
    float*  sbias = (float*)(dsm + 1536);
    __half* Ah    = (__half*)(dsm + OFF_AH);
    __half* Al    = (__half*)(dsm + OFF_AL);
    __half* Bh    = (__half*)(dsm + OFF_BH);
    __half* Bl    = (__half*)(dsm + OFF_BL);
    float*  Cst   = (float*)(dsm + OFF_AH);   // aliased; epilogue only

    const float* Aglob = IS_FFN1 ? Ain : (const float*)g_Hbuf;
    float*       Obuf  = IS_FFN1 ? g_Hbuf : g_Ybuf;

    const int e = blockIdx.z;
    const int cnt = g_cnt[e];
    const int m0 = blockIdx.y * 128;
    if (m0 >= cnt) return;
    const int n0 = blockIdx.x * 128;
    const float* W = Wg + (size_t)e * KTOT * NTOT;
    const int tid = threadIdx.x, w = tid >> 5;

    if (tid < 128) {
        int m = m0 + tid;
        int slot = (m < cnt) ? g_slots[e * Tc + m] : g_slots[e * Tc + cnt - 1];
        rslot[tid] = slot;
        rgate[tid] = g_gate[slot];
        rrow[tid]  = IS_FFN1 ? (slot >> 1) : slot;
        sbias[tid] = bias[(size_t)e * NTOT + n0 + tid];
    }
    __syncthreads();

    // loader roles
    const int ar = tid >> 1;            // A row 0..127
    const int ah = (tid & 1) * 16;      // A k-offset 0/16
    const float* pA = Aglob + (size_t)rrow[ar] * KTOT + ah;
    const int br = tid >> 3;            // B k-row 0..31
    const int bc = (tid & 7) * 16;      // B col seg
    const float* pB = W + (size_t)br * NTOT + n0 + bc;

    const int wm = (w >> 2) * 64;       // 0 / 64
    const int wn = (w & 3) * 32;        // 0 / 32 / 64 / 96

    wmma::fragment<wmma::accumulator, 16, 16, 16, float> cf[4][2];
#pragma unroll
    for (int mi = 0; mi < 4; mi++)
#pragma unroll
        for (int nb = 0; nb < 2; nb++) wmma::fill_fragment(cf[mi][nb], 0.f);

    for (int c = 0; c < NC; c++) {
        const int k0 = c * 32;
        __syncthreads();   // previous chunk fully consumed
        // A: 16 fp32 -> hi/lo halves
        {
            __half* dstH = Ah + ar * A_LD + ah;
            __half* dstL = Al + ar * A_LD + ah;
#pragma unroll
            for (int q = 0; q < 4; q++) {
                float4 v = *(const float4*)(pA + k0 + q * 4);
                float f[4] = {v.x, v.y, v.z, v.w};
#pragma unroll
                for (int j = 0; j < 4; j++) {
                    __half h = __float2half(f[j]);
                    dstH[q * 4 + j] = h;
                    dstL[q * 4 + j] = __float2half(f[j] - __half2float(h));
                }
            }
        }
        // B: 16 fp32 -> hi/lo halves
        {
            const float* src = pB + (size_t)k0 * NTOT;
            __half* dstH = Bh + br * B_LD + bc;
            __half* dstL = Bl + br * B_LD + bc;
#pragma unroll
            for (int q = 0; q < 4; q++) {
                float4 v = *(const float4*)(src + q * 4);
                float f[4] = {v.x, v.y, v.z, v.w};
#pragma unroll
                for (int j = 0; j < 4; j++) {
                    __half h = __float2half(f[j]);
                    dstH[q * 4 + j] = h;
                    dstL[q * 4 + j] = __float2half(f[j] - __half2float(h));
                }
            }
        }
        __syncthreads();

#pragma unroll
        for (int ks = 0; ks < 2; ks++) {
#pragma unroll
            for (int nb = 0; nb < 2; nb++) {
                wmma::fragment<wmma::matrix_b, 16, 16, 16, __half, wmma::row_major> bfh, bfl;
                wmma::load_matrix_sync(bfh, Bh + (ks * 16) * B_LD + wn + nb * 16, B_LD);
                wmma::load_matrix_sync(bfl, Bl + (ks * 16) * B_LD + wn + nb * 16, B_LD);
#pragma unroll
                for (int mi = 0; mi < 4; mi++) {
                    wmma::fragment<wmma::matrix_a, 16, 16, 16, __half, wmma::row_major> afh, afl;
                    wmma::load_matrix_sync(afh, Ah + (wm + mi * 16) * A_LD + ks * 16, A_LD);
                    wmma::load_matrix_sync(afl, Al + (wm + mi * 16) * A_LD + ks * 16, A_LD);
                    wmma::mma_sync(cf[mi][nb], afh, bfh, cf[mi][nb]);
                    wmma::mma_sync(cf[mi][nb], afl, bfh, cf[mi][nb]);
                    wmma::mma_sync(cf[mi][nb], afh, bfl, cf[mi][nb]);
                }
            }
        }
    }

    // ---------------- epilogue: 2 rounds of 64 rows via SMEM staging ----------------
    for (int r = 0; r < 2; r++) {
        __syncthreads();   // tile smem free (or previous round consumed)
        if ((w >> 2) == r) {
#pragma unroll
            for (int mi = 0; mi < 4; mi++)
#pragma unroll
                for (int nb = 0; nb < 2; nb++)
                    wmma::store_matrix_sync(
                        Cst + (wm - r * 64 + mi * 16) * C_LDM + wn + nb * 16,
                        cf[mi][nb], C_LDM, wmma::mem_row_major);
        }
        __syncthreads();

        for (int v = tid; v < 64 * 32; v += 256) {
            int row = v >> 5;
            int c4 = (v & 31) * 4;
            int m = m0 + r * 64 + row;
            if (m < cnt) {
                int slot = rslot[r * 64 + row];
                float vv[4];
#pragma unroll
                for (int j = 0; j < 4; j++)
                    vv[j] = Cst[row * C_LDM + c4 + j] + sbias[c4 + j];
                float4 y;
                if (IS_FFN1) {
                    y.x = 0.5f * vv[0] * (1.f + erff(vv[0] * 0.70710678118654752f));
                    y.y = 0.5f * vv[1] * (1.f + erff(vv[1] * 0.70710678118654752f));
                    y.z = 0.5f * vv[2] * (1.f + erff(vv[2] * 0.70710678118654752f));
                    y.w = 0.5f * vv[3] * (1.f + erff(vv[3] * 0.70710678118654752f));
                } else {
                    float gate = rgate[r * 64 + row];
                    y.x = gate * vv[0]; y.y = gate * vv[1];
                    y.z = gate * vv[2]; y.w = gate * vv[3];
                }
                *(float4*)(Obuf + (size_t)slot * NTOT + n0 + c4) = y;
            }
        }
    }
}

// ---------------- combine the two slots per token ----------------
__global__ void k_combine(float* __restrict__ out) {
    size_t i = (size_t)blockIdx.x * blockDim.x + threadIdx.x;
    const size_t nvec = (size_t)Tc * Dc / 4;
    if (i >= nvec) return;
    const size_t dq_per = Dc / 4;
    size_t t = i / dq_per, dq = i % dq_per;
    const float4 a = ((const float4*)g_Ybuf)[(2*t)   * dq_per + dq];
    const float4 b = ((const float4*)g_Ybuf)[(2*t+1) * dq_per + dq];
    float4 r; r.x = a.x + b.x; r.y = a.y + b.y; r.z = a.z + b.z; r.w = a.w + b.w;
    ((float4*)out)[i] = r;
}

// ---------------- aux scalar losses ----------------
__global__ void k_scalars(float* __restrict__ out) {
    if (threadIdx.x == 0 && blockIdx.x == 0) {
        const double invT = 1.0 / (double)Tc;
        double lb = 0.0;
        for (int e = 0; e < Ec; e++) {
            double imp = g_aux[e] * invT;
            double d = imp - 1.0 / Ec;
            lb += d * d;
        }
        lb /= Ec;
        double rz  = g_aux[Ec]     * invT;
        double ent = g_aux[Ec + 1] * invT;
        out[(size_t)Tc*Dc + 0] = (float)lb;
        out[(size_t)Tc*Dc + 1] = (float)rz;
        out[(size_t)Tc*Dc + 2] = (float)ent;
        out[(size_t)Tc*Dc + 3] = (float)(lb + 0.001 * rz - 0.001 * ent);
    }
}

// ---------------- launch ----------------
extern "C" void kernel_launch(void* const* d_in, const int* in_sizes, int n_in,
                              void* d_out, int out_size) {
    const float* x       = (const float*)d_in[0];
    const float* context = (const float*)d_in[1];
    const float* quality = (const float*)d_in[2];
    const float* rn_g    = (const float*)d_in[3];
    const float* rn_b    = (const float*)d_in[4];
    const float* cn_g    = (const float*)d_in[5];
    const float* cn_b    = (const float*)d_in[6];
    const float* ctx_W   = (const float*)d_in[7];
    const float* ctx_b   = (const float*)d_in[8];
    const float* q_W     = (const float*)d_in[9];
    const float* q_b     = (const float*)d_in[10];
    const float* r_W     = (const float*)d_in[11];
    const float* r_b     = (const float*)d_in[12];
    const float* temp_p  = (const float*)d_in[13];
    const float* W1      = (const float*)d_in[14];
    const float* b1      = (const float*)d_in[15];
    const float* W2      = (const float*)d_in[16];
    const float* b2      = (const float*)d_in[17];
    float* out = (float*)d_out;

    k_init<<<1, 32>>>();
    k_prep<<<Dc + 2, 256>>>(ctx_W, r_W, q_W, ctx_b, q_b, r_b);
    k_router<<<296, 256>>>(x, context, quality, rn_g, rn_b, cn_g, cn_b, r_W, temp_p);

    dim3 g1(Hc / 128, Tc / 128, Ec);   // 32 x 64 x 8
    k_ffn<true,  Dc, Hc><<<g1, 256, SM_TOTAL>>>(x, W1, b1);

    dim3 g2(Dc / 128, Tc / 128, Ec);   // 8 x 64 x 8
    k_ffn<false, Hc, Dc><<<g2, 256, SM_TOTAL>>>(nullptr, W2, b2);

    const size_t nvec = (size_t)Tc * Dc / 4;
    k_combine<<<(unsigned)((nvec + 255) / 256), 256>>>(out);
    k_scalars<<<1, 32>>>(out);
}